// round 2
// baseline (speedup 1.0000x reference)
#include <cuda_runtime.h>
#include <cstdint>

// Problem constants (fixed by the reference)
#define B_  8
#define C_  256
#define H_  64
#define W_  64
#define OC_ 256
#define KH_ 3
#define KW_ 3
#define K_  9
#define HW_ (H_ * W_)          // 4096
#define CK_ (C_ * K_)          // 2304

// Scratch (allocation-free rule: __device__ globals)
__device__ float g_cols[(size_t)B_ * CK_ * HW_];     // 302 MB: cols[b][c*9+k][pix]
__device__ float4 g_sw[B_ * K_ * HW_];               // bilinear weights (×mask)
__device__ int4   g_si[B_ * K_ * HW_];               // clamped corner indices

// ---------------------------------------------------------------------------
// Kernel 0: per (b,k,pixel) compute 4 corner indices + weights (bilinear×mask)
// ---------------------------------------------------------------------------
__global__ void prep_kernel(const float* __restrict__ offset,
                            const float* __restrict__ mask) {
    int gid = blockIdx.x * blockDim.x + threadIdx.x;   // 0 .. B*K*HW-1
    if (gid >= B_ * K_ * HW_) return;
    int pix = gid & (HW_ - 1);
    int bk  = gid >> 12;
    int k   = bk % K_;
    int b   = bk / K_;
    int ho  = pix >> 6;
    int wo  = pix & 63;

    float dy = offset[((size_t)(b * 18 + 2 * k) << 12) + pix];
    float dx = offset[((size_t)(b * 18 + 2 * k + 1) << 12) + pix];
    float m  = mask[((size_t)(b * 9 + k) << 12) + pix];

    float py = (float)(k / 3) + (float)(ho - 1) + dy;
    float px = (float)(k % 3) + (float)(wo - 1) + dx;

    float y0f = floorf(py);
    float x0f = floorf(px);
    float wy1 = py - y0f;
    float wx1 = px - x0f;
    float wy0 = 1.0f - wy1;
    float wx0 = 1.0f - wx1;
    int y0 = (int)y0f;
    int x0 = (int)x0f;
    int y1 = y0 + 1;
    int x1 = x0 + 1;

    // validity + clamp, weight *= valid, all folded with mask
    float v00 = (y0 >= 0 && y0 < H_ && x0 >= 0 && x0 < W_) ? 1.0f : 0.0f;
    float v01 = (y0 >= 0 && y0 < H_ && x1 >= 0 && x1 < W_) ? 1.0f : 0.0f;
    float v10 = (y1 >= 0 && y1 < H_ && x0 >= 0 && x0 < W_) ? 1.0f : 0.0f;
    float v11 = (y1 >= 0 && y1 < H_ && x1 >= 0 && x1 < W_) ? 1.0f : 0.0f;

    int yi0 = min(max(y0, 0), H_ - 1);
    int yi1 = min(max(y1, 0), H_ - 1);
    int xi0 = min(max(x0, 0), W_ - 1);
    int xi1 = min(max(x1, 0), W_ - 1);

    float4 w;
    w.x = wy0 * wx0 * v00 * m;
    w.y = wy0 * wx1 * v01 * m;
    w.z = wy1 * wx0 * v10 * m;
    w.w = wy1 * wx1 * v11 * m;
    int4 idx;
    idx.x = yi0 * W_ + xi0;
    idx.y = yi0 * W_ + xi1;
    idx.z = yi1 * W_ + xi0;
    idx.w = yi1 * W_ + xi1;

    g_sw[gid] = w;
    g_si[gid] = idx;
}

// ---------------------------------------------------------------------------
// Kernel 1: im2col — block = (b, 256-pixel tile); samp-info for all 9 taps
// held in registers; loop over c with 36 gathers per thread per c.
// cols layout: [b][c*9+k][pix]  (K-dim major, pixels contiguous)
// ---------------------------------------------------------------------------
__global__ void __launch_bounds__(256, 4)
im2col_kernel(const float* __restrict__ x) {
    int b   = blockIdx.y;
    int pix = blockIdx.x * 256 + threadIdx.x;

    int4   si[K_];
    float4 sw[K_];
#pragma unroll
    for (int k = 0; k < K_; k++) {
        int sidx = ((b * K_ + k) << 12) + pix;
        si[k] = g_si[sidx];
        sw[k] = g_sw[sidx];
    }

    const float* xb = x + ((size_t)b * C_ << 12);
    float* cb = g_cols + ((size_t)b * CK_ << 12) + pix;

    for (int c = 0; c < C_; c++) {
        const float* xp = xb + ((size_t)c << 12);
        float v[K_];
#pragma unroll
        for (int k = 0; k < K_; k++) {
            v[k] = sw[k].x * __ldg(xp + si[k].x)
                 + sw[k].y * __ldg(xp + si[k].y)
                 + sw[k].z * __ldg(xp + si[k].z)
                 + sw[k].w * __ldg(xp + si[k].w);
        }
#pragma unroll
        for (int k = 0; k < K_; k++) {
            cb[((size_t)(c * K_ + k)) << 12] = v[k];
        }
    }
}

// ---------------------------------------------------------------------------
// Kernel 2: GEMM  out[b][oc][pix] = sum_kk W[oc][kk] * cols[b][kk][pix] + bias
// M=256 (OC), N=4096 (pix), K=2304. Tile 128x128x16, 8x8 per thread, 256 thr.
// ---------------------------------------------------------------------------
#define BM 128
#define BN 128
#define BK 16

__global__ void __launch_bounds__(256, 2)
gemm_kernel(const float* __restrict__ weight,
            const float* __restrict__ bias,
            float* __restrict__ out) {
    __shared__ float As[BK][BM];   // transposed weight tile: As[kk][oc]
    __shared__ float Bs[BK][BN];   // cols tile: Bs[kk][pix]

    int b     = blockIdx.z;
    int nBase = blockIdx.x * BN;
    int mBase = blockIdx.y * BM;
    int tid   = threadIdx.x;
    int tx    = tid & 15;
    int ty    = tid >> 4;

    const float* colsB = g_cols + ((size_t)b * CK_ << 12);

    float acc[8][8];
#pragma unroll
    for (int i = 0; i < 8; i++)
#pragma unroll
        for (int j = 0; j < 8; j++) acc[i][j] = 0.0f;

    for (int kt = 0; kt < CK_; kt += BK) {
        // load A (weight) tile: 128 rows x 16 kk, transpose into As[kk][oc]
#pragma unroll
        for (int i = 0; i < 2; i++) {
            int v   = tid + i * 256;
            int row = v >> 2;            // 0..127
            int c4  = (v & 3) << 2;      // 0,4,8,12
            float4 w4 = *(const float4*)(weight + (size_t)(mBase + row) * CK_ + kt + c4);
            As[c4 + 0][row] = w4.x;
            As[c4 + 1][row] = w4.y;
            As[c4 + 2][row] = w4.z;
            As[c4 + 3][row] = w4.w;
        }
        // load B (cols) tile: 16 kk rows x 128 pix (rows contiguous)
#pragma unroll
        for (int i = 0; i < 2; i++) {
            int v   = tid + i * 256;
            int row = v >> 5;            // 0..15
            int c4  = (v & 31) << 2;     // 0..124
            *(float4*)&Bs[row][c4] =
                *(const float4*)(colsB + (((size_t)(kt + row)) << 12) + nBase + c4);
        }
        __syncthreads();

#pragma unroll
        for (int kk = 0; kk < BK; kk++) {
            float a[8], bb[8];
            *(float4*)&a[0]  = *(float4*)&As[kk][ty * 8];
            *(float4*)&a[4]  = *(float4*)&As[kk][ty * 8 + 4];
            *(float4*)&bb[0] = *(float4*)&Bs[kk][tx * 8];
            *(float4*)&bb[4] = *(float4*)&Bs[kk][tx * 8 + 4];
#pragma unroll
            for (int i = 0; i < 8; i++)
#pragma unroll
                for (int j = 0; j < 8; j++)
                    acc[i][j] += a[i] * bb[j];
        }
        __syncthreads();
    }

    // epilogue: + bias, write float4
#pragma unroll
    for (int i = 0; i < 8; i++) {
        int oc = mBase + ty * 8 + i;
        float bz = bias[oc];
        float* orow = out + (((size_t)b * OC_ + oc) << 12) + nBase + tx * 8;
        float4 o0, o1;
        o0.x = acc[i][0] + bz; o0.y = acc[i][1] + bz;
        o0.z = acc[i][2] + bz; o0.w = acc[i][3] + bz;
        o1.x = acc[i][4] + bz; o1.y = acc[i][5] + bz;
        o1.z = acc[i][6] + bz; o1.w = acc[i][7] + bz;
        *(float4*)(orow)     = o0;
        *(float4*)(orow + 4) = o1;
    }
}

// ---------------------------------------------------------------------------
extern "C" void kernel_launch(void* const* d_in, const int* in_sizes, int n_in,
                              void* d_out, int out_size) {
    const float* x      = (const float*)d_in[0];
    const float* offset = (const float*)d_in[1];
    const float* mask   = (const float*)d_in[2];
    const float* weight = (const float*)d_in[3];
    const float* bias   = (const float*)d_in[4];
    float* out          = (float*)d_out;

    // Kernel 0: sampling prep
    {
        int total = B_ * K_ * HW_;
        prep_kernel<<<(total + 255) / 256, 256>>>(offset, mask);
    }
    // Kernel 1: im2col
    {
        dim3 grid(HW_ / 256, B_);
        im2col_kernel<<<grid, 256>>>(x);
    }
    // Kernel 2: GEMM + bias
    {
        dim3 grid(HW_ / BN, OC_ / BM, B_);
        gemm_kernel<<<grid, 256>>>(weight, bias, out);
    }
}

// round 3
// speedup vs baseline: 1.0301x; 1.0301x over previous
#include <cuda_runtime.h>
#include <cstdint>

// Problem constants (fixed by the reference)
#define B_  8
#define C_  256
#define H_  64
#define W_  64
#define OC_ 256
#define KH_ 3
#define KW_ 3
#define K_  9
#define HW_ (H_ * W_)          // 4096
#define CK_ (C_ * K_)          // 2304

// Scratch (allocation-free rule: __device__ globals)
__device__ float g_cols[(size_t)B_ * CK_ * HW_];     // 302 MB: cols[b][c*9+k][pix]
__device__ float4 g_sw[B_ * K_ * HW_];               // bilinear weights (×mask)
__device__ int4   g_si[B_ * K_ * HW_];               // clamped corner indices

// ---------------------------------------------------------------------------
// Kernel 0: per (b,k,pixel) compute 4 corner indices + weights (bilinear×mask)
// ---------------------------------------------------------------------------
__global__ void prep_kernel(const float* __restrict__ offset,
                            const float* __restrict__ mask) {
    int gid = blockIdx.x * blockDim.x + threadIdx.x;   // 0 .. B*K*HW-1
    if (gid >= B_ * K_ * HW_) return;
    int pix = gid & (HW_ - 1);
    int bk  = gid >> 12;
    int k   = bk % K_;
    int b   = bk / K_;
    int ho  = pix >> 6;
    int wo  = pix & 63;

    float dy = offset[((size_t)(b * 18 + 2 * k) << 12) + pix];
    float dx = offset[((size_t)(b * 18 + 2 * k + 1) << 12) + pix];
    float m  = mask[((size_t)(b * 9 + k) << 12) + pix];

    float py = (float)(k / 3) + (float)(ho - 1) + dy;
    float px = (float)(k % 3) + (float)(wo - 1) + dx;

    float y0f = floorf(py);
    float x0f = floorf(px);
    float wy1 = py - y0f;
    float wx1 = px - x0f;
    float wy0 = 1.0f - wy1;
    float wx0 = 1.0f - wx1;
    int y0 = (int)y0f;
    int x0 = (int)x0f;
    int y1 = y0 + 1;
    int x1 = x0 + 1;

    // validity + clamp, weight *= valid, all folded with mask
    float v00 = (y0 >= 0 && y0 < H_ && x0 >= 0 && x0 < W_) ? 1.0f : 0.0f;
    float v01 = (y0 >= 0 && y0 < H_ && x1 >= 0 && x1 < W_) ? 1.0f : 0.0f;
    float v10 = (y1 >= 0 && y1 < H_ && x0 >= 0 && x0 < W_) ? 1.0f : 0.0f;
    float v11 = (y1 >= 0 && y1 < H_ && x1 >= 0 && x1 < W_) ? 1.0f : 0.0f;

    int yi0 = min(max(y0, 0), H_ - 1);
    int yi1 = min(max(y1, 0), H_ - 1);
    int xi0 = min(max(x0, 0), W_ - 1);
    int xi1 = min(max(x1, 0), W_ - 1);

    float4 w;
    w.x = wy0 * wx0 * v00 * m;
    w.y = wy0 * wx1 * v01 * m;
    w.z = wy1 * wx0 * v10 * m;
    w.w = wy1 * wx1 * v11 * m;
    int4 idx;
    idx.x = yi0 * W_ + xi0;
    idx.y = yi0 * W_ + xi1;
    idx.z = yi1 * W_ + xi0;
    idx.w = yi1 * W_ + xi1;

    g_sw[gid] = w;
    g_si[gid] = idx;
}

// ---------------------------------------------------------------------------
// Kernel 1: im2col — block = (b, 256-pixel tile); samp-info for all 9 taps
// held in registers; loop over c with 36 gathers per thread per c.
// cols layout: [b][c*9+k][pix]  (K-dim major, pixels contiguous)
// ---------------------------------------------------------------------------
__global__ void __launch_bounds__(256, 4)
im2col_kernel(const float* __restrict__ x) {
    int b   = blockIdx.y;
    int pix = blockIdx.x * 256 + threadIdx.x;

    int4   si[K_];
    float4 sw[K_];
#pragma unroll
    for (int k = 0; k < K_; k++) {
        int sidx = ((b * K_ + k) << 12) + pix;
        si[k] = g_si[sidx];
        sw[k] = g_sw[sidx];
    }

    const float* xb = x + ((size_t)b * C_ << 12);
    float* cb = g_cols + ((size_t)b * CK_ << 12) + pix;

    for (int c = 0; c < C_; c++) {
        const float* xp = xb + ((size_t)c << 12);
        float v[K_];
#pragma unroll
        for (int k = 0; k < K_; k++) {
            v[k] = sw[k].x * __ldg(xp + si[k].x)
                 + sw[k].y * __ldg(xp + si[k].y)
                 + sw[k].z * __ldg(xp + si[k].z)
                 + sw[k].w * __ldg(xp + si[k].w);
        }
#pragma unroll
        for (int k = 0; k < K_; k++) {
            cb[((size_t)(c * K_ + k)) << 12] = v[k];
        }
    }
}

// ---------------------------------------------------------------------------
// Kernel 2: GEMM  out[b][oc][pix] = sum_kk W[oc][kk] * cols[b][kk][pix] + bias
// M=256 (OC), N=4096 (pix), K=2304. Tile 128x128x16, 8x8 per thread, 256 thr.
// ---------------------------------------------------------------------------
#define BM 128
#define BN 128
#define BK 16

__global__ void __launch_bounds__(256, 2)
gemm_kernel(const float* __restrict__ weight,
            const float* __restrict__ bias,
            float* __restrict__ out) {
    __shared__ float As[BK][BM];   // transposed weight tile: As[kk][oc]
    __shared__ float Bs[BK][BN];   // cols tile: Bs[kk][pix]

    int b     = blockIdx.z;
    int nBase = blockIdx.x * BN;
    int mBase = blockIdx.y * BM;
    int tid   = threadIdx.x;
    int tx    = tid & 15;
    int ty    = tid >> 4;

    const float* colsB = g_cols + ((size_t)b * CK_ << 12);

    float acc[8][8];
#pragma unroll
    for (int i = 0; i < 8; i++)
#pragma unroll
        for (int j = 0; j < 8; j++) acc[i][j] = 0.0f;

    for (int kt = 0; kt < CK_; kt += BK) {
        // load A (weight) tile: 128 rows x 16 kk, transpose into As[kk][oc]
#pragma unroll
        for (int i = 0; i < 2; i++) {
            int v   = tid + i * 256;
            int row = v >> 2;            // 0..127
            int c4  = (v & 3) << 2;      // 0,4,8,12
            float4 w4 = *(const float4*)(weight + (size_t)(mBase + row) * CK_ + kt + c4);
            As[c4 + 0][row] = w4.x;
            As[c4 + 1][row] = w4.y;
            As[c4 + 2][row] = w4.z;
            As[c4 + 3][row] = w4.w;
        }
        // load B (cols) tile: 16 kk rows x 128 pix (rows contiguous)
#pragma unroll
        for (int i = 0; i < 2; i++) {
            int v   = tid + i * 256;
            int row = v >> 5;            // 0..15
            int c4  = (v & 31) << 2;     // 0..124
            *(float4*)&Bs[row][c4] =
                *(const float4*)(colsB + (((size_t)(kt + row)) << 12) + nBase + c4);
        }
        __syncthreads();

#pragma unroll
        for (int kk = 0; kk < BK; kk++) {
            float a[8], bb[8];
            *(float4*)&a[0]  = *(float4*)&As[kk][ty * 8];
            *(float4*)&a[4]  = *(float4*)&As[kk][ty * 8 + 4];
            *(float4*)&bb[0] = *(float4*)&Bs[kk][tx * 8];
            *(float4*)&bb[4] = *(float4*)&Bs[kk][tx * 8 + 4];
#pragma unroll
            for (int i = 0; i < 8; i++)
#pragma unroll
                for (int j = 0; j < 8; j++)
                    acc[i][j] += a[i] * bb[j];
        }
        __syncthreads();
    }

    // epilogue: + bias, write float4
#pragma unroll
    for (int i = 0; i < 8; i++) {
        int oc = mBase + ty * 8 + i;
        float bz = bias[oc];
        float* orow = out + (((size_t)b * OC_ + oc) << 12) + nBase + tx * 8;
        float4 o0, o1;
        o0.x = acc[i][0] + bz; o0.y = acc[i][1] + bz;
        o0.z = acc[i][2] + bz; o0.w = acc[i][3] + bz;
        o1.x = acc[i][4] + bz; o1.y = acc[i][5] + bz;
        o1.z = acc[i][6] + bz; o1.w = acc[i][7] + bz;
        *(float4*)(orow)     = o0;
        *(float4*)(orow + 4) = o1;
    }
}

// ---------------------------------------------------------------------------
extern "C" void kernel_launch(void* const* d_in, const int* in_sizes, int n_in,
                              void* d_out, int out_size) {
    const float* x      = (const float*)d_in[0];
    const float* offset = (const float*)d_in[1];
    const float* mask   = (const float*)d_in[2];
    const float* weight = (const float*)d_in[3];
    const float* bias   = (const float*)d_in[4];
    float* out          = (float*)d_out;

    // Kernel 0: sampling prep
    {
        int total = B_ * K_ * HW_;
        prep_kernel<<<(total + 255) / 256, 256>>>(offset, mask);
    }
    // Kernel 1: im2col
    {
        dim3 grid(HW_ / 256, B_);
        im2col_kernel<<<grid, 256>>>(x);
    }
    // Kernel 2: GEMM + bias
    {
        dim3 grid(HW_ / BN, OC_ / BM, B_);
        gemm_kernel<<<grid, 256>>>(weight, bias, out);
    }
}

// round 6
// speedup vs baseline: 1.5820x; 1.5358x over previous
#include <cuda_runtime.h>
#include <cuda_bf16.h>
#include <cstdint>

// Problem constants
#define B_   8
#define C_   256
#define H_   64
#define W_   64
#define OC_  256
#define K_   9
#define HW_  4096
#define CK_  2304

// ---------------------------------------------------------------------------
// Device scratch (allocation-free rule)
// ---------------------------------------------------------------------------
__device__ __align__(256) __nv_bfloat16 g_colsHi[(size_t)B_ * CK_ * HW_]; // 151MB
__device__ __align__(256) __nv_bfloat16 g_colsLo[(size_t)B_ * CK_ * HW_]; // 151MB
__device__ __align__(256) __nv_bfloat16 g_wHi[OC_ * CK_];
__device__ __align__(256) __nv_bfloat16 g_wLo[OC_ * CK_];
__device__ float4 g_sw[B_ * K_ * HW_];
__device__ int4   g_si[B_ * K_ * HW_];

// ---------------------------------------------------------------------------
// Helpers
// ---------------------------------------------------------------------------
__device__ __forceinline__ uint32_t smem_u32(const void* p) {
    uint32_t a;
    asm("{ .reg .u64 t; cvta.to.shared.u64 t, %1; cvt.u32.u64 %0, t; }"
        : "=r"(a) : "l"(p));
    return a;
}

__device__ __forceinline__ void cpasync16(uint32_t s, const void* g) {
    asm volatile("cp.async.cg.shared.global [%0], [%1], 16;" :: "r"(s), "l"(g));
}

__device__ __forceinline__ void ldsm_x4(uint32_t* r, uint32_t addr) {
    asm volatile("ldmatrix.sync.aligned.m8n8.x4.shared.b16 {%0,%1,%2,%3}, [%4];"
                 : "=r"(r[0]), "=r"(r[1]), "=r"(r[2]), "=r"(r[3]) : "r"(addr));
}

__device__ __forceinline__ void ldsm_x4_t(uint32_t* r, uint32_t addr) {
    asm volatile("ldmatrix.sync.aligned.m8n8.x4.trans.shared.b16 {%0,%1,%2,%3}, [%4];"
                 : "=r"(r[0]), "=r"(r[1]), "=r"(r[2]), "=r"(r[3]) : "r"(addr));
}

__device__ __forceinline__ void mma_bf16(float* d, const uint32_t* a,
                                         uint32_t b0, uint32_t b1) {
    asm volatile(
        "mma.sync.aligned.m16n8k16.row.col.f32.bf16.bf16.f32 "
        "{%0,%1,%2,%3}, {%4,%5,%6,%7}, {%8,%9}, {%0,%1,%2,%3};"
        : "+f"(d[0]), "+f"(d[1]), "+f"(d[2]), "+f"(d[3])
        : "r"(a[0]), "r"(a[1]), "r"(a[2]), "r"(a[3]), "r"(b0), "r"(b1));
}

// ---------------------------------------------------------------------------
// Kernel 0: sampling prep (indices + weights*mask)
// ---------------------------------------------------------------------------
__global__ void prep_kernel(const float* __restrict__ offset,
                            const float* __restrict__ mask) {
    int gid = blockIdx.x * blockDim.x + threadIdx.x;
    if (gid >= B_ * K_ * HW_) return;
    int pix = gid & (HW_ - 1);
    int bk  = gid >> 12;
    int k   = bk % K_;
    int b   = bk / K_;
    int ho  = pix >> 6;
    int wo  = pix & 63;

    float dy = offset[((size_t)(b * 18 + 2 * k) << 12) + pix];
    float dx = offset[((size_t)(b * 18 + 2 * k + 1) << 12) + pix];
    float m  = mask[((size_t)(b * 9 + k) << 12) + pix];

    float py = (float)(k / 3) + (float)(ho - 1) + dy;
    float px = (float)(k % 3) + (float)(wo - 1) + dx;

    float y0f = floorf(py), x0f = floorf(px);
    float wy1 = py - y0f, wx1 = px - x0f;
    float wy0 = 1.0f - wy1, wx0 = 1.0f - wx1;
    int y0 = (int)y0f, x0 = (int)x0f;
    int y1 = y0 + 1, x1 = x0 + 1;

    float v00 = (y0 >= 0 && y0 < H_ && x0 >= 0 && x0 < W_) ? 1.0f : 0.0f;
    float v01 = (y0 >= 0 && y0 < H_ && x1 >= 0 && x1 < W_) ? 1.0f : 0.0f;
    float v10 = (y1 >= 0 && y1 < H_ && x0 >= 0 && x0 < W_) ? 1.0f : 0.0f;
    float v11 = (y1 >= 0 && y1 < H_ && x1 >= 0 && x1 < W_) ? 1.0f : 0.0f;

    int yi0 = min(max(y0, 0), H_ - 1), yi1 = min(max(y1, 0), H_ - 1);
    int xi0 = min(max(x0, 0), W_ - 1), xi1 = min(max(x1, 0), W_ - 1);

    float4 w;
    w.x = wy0 * wx0 * v00 * m;
    w.y = wy0 * wx1 * v01 * m;
    w.z = wy1 * wx0 * v10 * m;
    w.w = wy1 * wx1 * v11 * m;
    int4 idx;
    idx.x = yi0 * W_ + xi0;
    idx.y = yi0 * W_ + xi1;
    idx.z = yi1 * W_ + xi0;
    idx.w = yi1 * W_ + xi1;

    g_sw[gid] = w;
    g_si[gid] = idx;
}

// ---------------------------------------------------------------------------
// Kernel 1: split weight into bf16 hi/lo (separate arrays)
// ---------------------------------------------------------------------------
__global__ void wsplit_kernel(const float* __restrict__ w) {
    int i = blockIdx.x * blockDim.x + threadIdx.x;
    if (i >= OC_ * CK_) return;
    float v = w[i];
    __nv_bfloat16 h = __float2bfloat16(v);
    float residual = v - __bfloat162float(h);
    g_wHi[i] = h;
    g_wLo[i] = __float2bfloat16(residual);
}

// ---------------------------------------------------------------------------
// Kernel 2: im2col -> bf16 hi/lo cols [b][c*9+k][pix], separate arrays
// ---------------------------------------------------------------------------
__global__ void __launch_bounds__(256, 4)
im2col_kernel(const float* __restrict__ x) {
    int b   = blockIdx.y;
    int pix = blockIdx.x * 256 + threadIdx.x;

    int4   si[K_];
    float4 sw[K_];
#pragma unroll
    for (int k = 0; k < K_; k++) {
        int sidx = ((b * K_ + k) << 12) + pix;
        si[k] = g_si[sidx];
        sw[k] = g_sw[sidx];
    }

    const float* xb = x + ((size_t)b * C_ << 12);
    size_t base = ((size_t)b * CK_ << 12) + pix;

    for (int c = 0; c < C_; c++) {
        const float* xp = xb + ((size_t)c << 12);
        float v[K_];
#pragma unroll
        for (int k = 0; k < K_; k++) {
            v[k] = sw[k].x * __ldg(xp + si[k].x)
                 + sw[k].y * __ldg(xp + si[k].y)
                 + sw[k].z * __ldg(xp + si[k].z)
                 + sw[k].w * __ldg(xp + si[k].w);
        }
#pragma unroll
        for (int k = 0; k < K_; k++) {
            size_t o = base + (((size_t)(c * K_ + k)) << 12);
            __nv_bfloat16 h = __float2bfloat16(v[k]);
            float residual = v[k] - __bfloat162float(h);
            g_colsHi[o] = h;
            g_colsLo[o] = __float2bfloat16(residual);
        }
    }
}

// ---------------------------------------------------------------------------
// Kernel 3: bf16 HMMA GEMM, 3 products: AhiBhi + AhiBlo + AloBhi.
// out[b][oc][pix] = sum_ck W[oc][ck]*cols[b][ck][pix] + bias[oc]
// M=256, N=4096 (per b), K=2304. CTA 128x128, BK=16, 8 warps (2x4),
// warp tile 64x32. cp.async double buffer, ldmatrix, m16n8k16.
// ---------------------------------------------------------------------------
#define BK   16
#define NKIT (CK_ / BK)      // 144
#define APAD 8
#define BPAD 8

__global__ void __launch_bounds__(256, 2)
gemm_mma_kernel(const float* __restrict__ bias, float* __restrict__ out) {
    // [stage][part(hi/lo)][row][col]
    __shared__ __align__(16) __nv_bfloat16 As[2][2][128][BK + APAD];  // 24 KB
    __shared__ __align__(16) __nv_bfloat16 Bs[2][2][BK][128 + BPAD];  // 17 KB

    const int tid   = threadIdx.x;
    const int wid   = tid >> 5;
    const int lid   = tid & 31;
    const int wm    = wid >> 2;        // 0..1
    const int wn    = wid & 3;         // 0..3
    const int nBase = blockIdx.x * 128;
    const int mBase = blockIdx.y * 128;
    const int b     = blockIdx.z;

    const __nv_bfloat16* colsHiB = g_colsHi + ((size_t)b * CK_ << 12);
    const __nv_bfloat16* colsLoB = g_colsLo + ((size_t)b * CK_ << 12);

    float acc[4][4][4];
#pragma unroll
    for (int i = 0; i < 4; i++)
#pragma unroll
        for (int j = 0; j < 4; j++)
#pragma unroll
            for (int q = 0; q < 4; q++) acc[i][j][q] = 0.0f;

    // async load of one stage: each thread does 4 x 16B (2 A parts, 2 B parts)
    auto load_stage = [&](int s, int kt) {
        {   // A hi: 128 rows x 16 ck (32B/row = 2 chunks)
            int row = tid >> 1, seg = tid & 1;
            cpasync16(smem_u32(&As[s][0][row][seg * 8]),
                      g_wHi + (size_t)(mBase + row) * CK_ + kt + seg * 8);
            cpasync16(smem_u32(&As[s][1][row][seg * 8]),
                      g_wLo + (size_t)(mBase + row) * CK_ + kt + seg * 8);
        }
        {   // B: 16 rows x 128 (256B/row = 16 chunks)
            int row = tid >> 4, seg = tid & 15;
            size_t g = (((size_t)(kt + row)) << 12) + nBase + seg * 8;
            cpasync16(smem_u32(&Bs[s][0][row][seg * 8]), colsHiB + g);
            cpasync16(smem_u32(&Bs[s][1][row][seg * 8]), colsLoB + g);
        }
        asm volatile("cp.async.commit_group;" ::: "memory");
    };

    load_stage(0, 0);

    for (int i = 0; i < NKIT; i++) {
        int s = i & 1;
        if (i + 1 < NKIT) {
            load_stage(s ^ 1, (i + 1) * BK);
            asm volatile("cp.async.wait_group 1;" ::: "memory");
        } else {
            asm volatile("cp.async.wait_group 0;" ::: "memory");
        }
        __syncthreads();

        // A fragments: [part][mt]
        uint32_t a[2][4][4];
#pragma unroll
        for (int p = 0; p < 2; p++)
#pragma unroll
            for (int mt = 0; mt < 4; mt++) {
                uint32_t addr = smem_u32(
                    &As[s][p][wm * 64 + mt * 16 + (lid & 15)][((lid >> 4) & 1) * 8]);
                ldsm_x4(a[p][mt], addr);
            }
        // B fragments: [part][pr] (pr covers n16 via x4.trans)
        uint32_t bf[2][2][4];
#pragma unroll
        for (int p = 0; p < 2; p++)
#pragma unroll
            for (int pr = 0; pr < 2; pr++) {
                uint32_t addr = smem_u32(
                    &Bs[s][p][lid & 15][wn * 32 + pr * 16 + ((lid >> 4) & 1) * 8]);
                ldsm_x4_t(bf[p][pr], addr);
            }

#pragma unroll
        for (int mt = 0; mt < 4; mt++)
#pragma unroll
            for (int nt = 0; nt < 4; nt++) {
                uint32_t bh0 = bf[0][nt >> 1][(nt & 1) * 2];
                uint32_t bh1 = bf[0][nt >> 1][(nt & 1) * 2 + 1];
                uint32_t bl0 = bf[1][nt >> 1][(nt & 1) * 2];
                uint32_t bl1 = bf[1][nt >> 1][(nt & 1) * 2 + 1];
                mma_bf16(acc[mt][nt], a[0][mt], bh0, bh1);   // hi*hi
                mma_bf16(acc[mt][nt], a[0][mt], bl0, bl1);   // hi*lo
                mma_bf16(acc[mt][nt], a[1][mt], bh0, bh1);   // lo*hi
            }
        __syncthreads();
    }

    // Epilogue
    const int r  = lid >> 2;
    const int cc = (lid & 3) * 2;
#pragma unroll
    for (int mt = 0; mt < 4; mt++) {
        int oc0 = mBase + wm * 64 + mt * 16 + r;
        float bz0 = bias[oc0];
        float bz1 = bias[oc0 + 8];
        float* o0 = out + (((size_t)(b * OC_ + oc0)) << 12) + nBase;
        float* o1 = out + (((size_t)(b * OC_ + oc0 + 8)) << 12) + nBase;
#pragma unroll
        for (int nt = 0; nt < 4; nt++) {
            int px = wn * 32 + nt * 8 + cc;
            float2 v0 = make_float2(acc[mt][nt][0] + bz0, acc[mt][nt][1] + bz0);
            float2 v1 = make_float2(acc[mt][nt][2] + bz1, acc[mt][nt][3] + bz1);
            *(float2*)(o0 + px) = v0;
            *(float2*)(o1 + px) = v1;
        }
    }
}

// ---------------------------------------------------------------------------
extern "C" void kernel_launch(void* const* d_in, const int* in_sizes, int n_in,
                              void* d_out, int out_size) {
    const float* x      = (const float*)d_in[0];
    const float* offset = (const float*)d_in[1];
    const float* mask   = (const float*)d_in[2];
    const float* weight = (const float*)d_in[3];
    const float* bias   = (const float*)d_in[4];
    float* out          = (float*)d_out;

    prep_kernel<<<(B_ * K_ * HW_ + 255) / 256, 256>>>(offset, mask);
    wsplit_kernel<<<(OC_ * CK_ + 255) / 256, 256>>>(weight);
    {
        dim3 grid(HW_ / 256, B_);
        im2col_kernel<<<grid, 256>>>(x);
    }
    {
        dim3 grid(HW_ / 128, OC_ / 128, B_);
        gemm_mma_kernel<<<grid, 256>>>(bias, out);
    }
}

// round 7
// speedup vs baseline: 6.0017x; 3.7937x over previous
#include <cuda_runtime.h>
#include <cuda_fp16.h>
#include <cstdint>

// Problem constants
#define B_   8
#define C_   256
#define H_   64
#define W_   64
#define OC_  256
#define K_   9
#define HW_  4096
#define CK_  2304

// ---------------------------------------------------------------------------
// Device scratch (allocation-free rule)
// ---------------------------------------------------------------------------
__device__ __align__(256) __half g_cols[(size_t)B_ * CK_ * HW_];  // 151 MB, [b][k*256+c][pix]
__device__ __align__(256) __half g_w[OC_ * CK_];                  // [oc][k*256+c]
__device__ __align__(256) float  g_xt[(size_t)B_ * HW_ * C_];     // 134 MB, [b][pix][c]
__device__ float4 g_sw[B_ * K_ * HW_];
__device__ int4   g_si[B_ * K_ * HW_];

// ---------------------------------------------------------------------------
// Helpers
// ---------------------------------------------------------------------------
__device__ __forceinline__ uint32_t smem_u32(const void* p) {
    uint32_t a;
    asm("{ .reg .u64 t; cvta.to.shared.u64 t, %1; cvt.u32.u64 %0, t; }"
        : "=r"(a) : "l"(p));
    return a;
}

__device__ __forceinline__ void cpasync16(uint32_t s, const void* g) {
    asm volatile("cp.async.cg.shared.global [%0], [%1], 16;" :: "r"(s), "l"(g));
}

__device__ __forceinline__ void ldsm_x4(uint32_t* r, uint32_t addr) {
    asm volatile("ldmatrix.sync.aligned.m8n8.x4.shared.b16 {%0,%1,%2,%3}, [%4];"
                 : "=r"(r[0]), "=r"(r[1]), "=r"(r[2]), "=r"(r[3]) : "r"(addr));
}

__device__ __forceinline__ void ldsm_x4_t(uint32_t* r, uint32_t addr) {
    asm volatile("ldmatrix.sync.aligned.m8n8.x4.trans.shared.b16 {%0,%1,%2,%3}, [%4];"
                 : "=r"(r[0]), "=r"(r[1]), "=r"(r[2]), "=r"(r[3]) : "r"(addr));
}

__device__ __forceinline__ void mma_f16(float* d, const uint32_t* a,
                                        uint32_t b0, uint32_t b1) {
    asm volatile(
        "mma.sync.aligned.m16n8k16.row.col.f32.f16.f16.f32 "
        "{%0,%1,%2,%3}, {%4,%5,%6,%7}, {%8,%9}, {%0,%1,%2,%3};"
        : "+f"(d[0]), "+f"(d[1]), "+f"(d[2]), "+f"(d[3])
        : "r"(a[0]), "r"(a[1]), "r"(a[2]), "r"(a[3]), "r"(b0), "r"(b1));
}

// ---------------------------------------------------------------------------
// Kernel 0: sampling prep (indices + weights*mask)
// ---------------------------------------------------------------------------
__global__ void prep_kernel(const float* __restrict__ offset,
                            const float* __restrict__ mask) {
    int gid = blockIdx.x * blockDim.x + threadIdx.x;
    if (gid >= B_ * K_ * HW_) return;
    int pix = gid & (HW_ - 1);
    int bk  = gid >> 12;
    int k   = bk % K_;
    int b   = bk / K_;
    int ho  = pix >> 6;
    int wo  = pix & 63;

    float dy = offset[((size_t)(b * 18 + 2 * k) << 12) + pix];
    float dx = offset[((size_t)(b * 18 + 2 * k + 1) << 12) + pix];
    float m  = mask[((size_t)(b * 9 + k) << 12) + pix];

    float py = (float)(k / 3) + (float)(ho - 1) + dy;
    float px = (float)(k % 3) + (float)(wo - 1) + dx;

    float y0f = floorf(py), x0f = floorf(px);
    float wy1 = py - y0f, wx1 = px - x0f;
    float wy0 = 1.0f - wy1, wx0 = 1.0f - wx1;
    int y0 = (int)y0f, x0 = (int)x0f;
    int y1 = y0 + 1, x1 = x0 + 1;

    float v00 = (y0 >= 0 && y0 < H_ && x0 >= 0 && x0 < W_) ? 1.0f : 0.0f;
    float v01 = (y0 >= 0 && y0 < H_ && x1 >= 0 && x1 < W_) ? 1.0f : 0.0f;
    float v10 = (y1 >= 0 && y1 < H_ && x0 >= 0 && x0 < W_) ? 1.0f : 0.0f;
    float v11 = (y1 >= 0 && y1 < H_ && x1 >= 0 && x1 < W_) ? 1.0f : 0.0f;

    int yi0 = min(max(y0, 0), H_ - 1), yi1 = min(max(y1, 0), H_ - 1);
    int xi0 = min(max(x0, 0), W_ - 1), xi1 = min(max(x1, 0), W_ - 1);

    float4 w;
    w.x = wy0 * wx0 * v00 * m;
    w.y = wy0 * wx1 * v01 * m;
    w.z = wy1 * wx0 * v10 * m;
    w.w = wy1 * wx1 * v11 * m;
    int4 idx;
    idx.x = yi0 * W_ + xi0;
    idx.y = yi0 * W_ + xi1;
    idx.z = yi1 * W_ + xi0;
    idx.w = yi1 * W_ + xi1;

    g_sw[gid] = w;
    g_si[gid] = idx;
}

// ---------------------------------------------------------------------------
// Kernel 1: weight -> fp16, reorder K dim to k*256+c
// src: weight[oc][c][k] ; dst: g_w[oc][k*256+c]
// ---------------------------------------------------------------------------
__global__ void wsplit_kernel(const float* __restrict__ w) {
    int i = blockIdx.x * blockDim.x + threadIdx.x;
    if (i >= OC_ * CK_) return;
    int oc  = i / CK_;
    int rem = i % CK_;
    int c   = rem / K_;
    int k   = rem % K_;
    g_w[(size_t)oc * CK_ + k * C_ + c] = __float2half(w[i]);
}

// ---------------------------------------------------------------------------
// Kernel 2: transpose x (B,C,HW) -> g_xt (B,HW,C)
// ---------------------------------------------------------------------------
__global__ void __launch_bounds__(256)
transpose_kernel(const float* __restrict__ x) {
    __shared__ float tile[32][33];
    int b  = blockIdx.z;
    int ct = blockIdx.y;      // c tile (8)
    int pt = blockIdx.x;      // pix tile (128)
    int tx  = threadIdx.x & 31;
    int ty4 = (threadIdx.x >> 5) * 4;

    const float* xb = x + (((size_t)(b * C_ + ct * 32)) << 12) + pt * 32;
#pragma unroll
    for (int i = 0; i < 4; i++)
        tile[ty4 + i][tx] = xb[((size_t)(ty4 + i) << 12) + tx];
    __syncthreads();
    float* xtb = g_xt + ((size_t)(b * HW_) + pt * 32) * C_ + ct * 32;
#pragma unroll
    for (int i = 0; i < 4; i++)
        xtb[(size_t)(ty4 + i) * C_ + tx] = tile[tx][ty4 + i];
}

// ---------------------------------------------------------------------------
// Kernel 3: im2col v2 — coalesced gathers along c from g_xt.
// CTA = (b, 32-pixel tile). Per k: each warp computes 4 pixels x 256 c
// (fully coalesced corner loads), stages fp16 in smem, then the CTA writes
// 256 rows (row = k*256+c) x 32 pix coalesced to g_cols.
// ---------------------------------------------------------------------------
__global__ void __launch_bounds__(256, 4)
im2col_kernel() {
    __shared__ __half stage[32][258];
    int b   = blockIdx.y;
    int p0  = blockIdx.x * 32;
    int tid = threadIdx.x;
    int wid = tid >> 5;
    int lid = tid & 31;

    const float* xb = g_xt + ((size_t)b * HW_) * C_;
    size_t colsBase = (size_t)b * CK_ * (size_t)HW_;

    for (int k = 0; k < K_; k++) {
#pragma unroll
        for (int p4 = 0; p4 < 4; p4++) {
            int p    = wid * 4 + p4;
            int pixg = p0 + p;
            int sidx = ((b * K_ + k) << 12) + pixg;
            int4   si = __ldg(&g_si[sidx]);
            float4 wv = __ldg(&g_sw[sidx]);
            int co = lid * 4;

            float a0x = 0.f, a0y = 0.f, a0z = 0.f, a0w = 0.f;
            float a1x = 0.f, a1y = 0.f, a1z = 0.f, a1w = 0.f;

            const float* cp;
            float4 v;
#define CORNER(IDX, WW)                                                        \
            cp = xb + ((size_t)(IDX) << 8) + co;                               \
            v = *(const float4*)cp;                                            \
            a0x += (WW) * v.x; a0y += (WW) * v.y;                              \
            a0z += (WW) * v.z; a0w += (WW) * v.w;                              \
            v = *(const float4*)(cp + 128);                                    \
            a1x += (WW) * v.x; a1y += (WW) * v.y;                              \
            a1z += (WW) * v.z; a1w += (WW) * v.w;

            CORNER(si.x, wv.x)
            CORNER(si.y, wv.y)
            CORNER(si.z, wv.z)
            CORNER(si.w, wv.w)
#undef CORNER

            *(__half2*)&stage[p][co]       = __floats2half2_rn(a0x, a0y);
            *(__half2*)&stage[p][co + 2]   = __floats2half2_rn(a0z, a0w);
            *(__half2*)&stage[p][co + 128] = __floats2half2_rn(a1x, a1y);
            *(__half2*)&stage[p][co + 130] = __floats2half2_rn(a1z, a1w);
        }
        __syncthreads();

        // write 256 rows x 32 pix: warp handles rows c = wid*32 + j
        __half* dst = g_cols + colsBase + (((size_t)(k * C_)) << 12) + p0 + lid;
#pragma unroll
        for (int j = 0; j < 32; j++) {
            int c = wid * 32 + j;
            dst[((size_t)c) << 12] = stage[lid][c];
        }
        __syncthreads();
    }
}

// ---------------------------------------------------------------------------
// Kernel 4: fp16 HMMA GEMM (single product).
// out[b][oc][pix] = sum_k' g_w[oc][k'] * g_cols[b][k'][pix] + bias[oc]
// M=256, N=4096 per b, K=2304. CTA 128x128, BK=32, 8 warps (2x4),
// warp tile 64x32. cp.async double buffer, ldmatrix, m16n8k16 f16.
// ---------------------------------------------------------------------------
#define BKG  32
#define NKIT (CK_ / BKG)     // 72
#define APAD 8
#define BPAD 8

__global__ void __launch_bounds__(256, 2)
gemm_mma_kernel(const float* __restrict__ bias, float* __restrict__ out) {
    __shared__ __align__(16) __half As[2][128][BKG + APAD];   // 20 KB
    __shared__ __align__(16) __half Bs[2][BKG][128 + BPAD];   // 17 KB

    const int tid   = threadIdx.x;
    const int wid   = tid >> 5;
    const int lid   = tid & 31;
    const int wm    = wid >> 2;        // 0..1
    const int wn    = wid & 3;         // 0..3
    const int nBase = blockIdx.x * 128;
    const int mBase = blockIdx.y * 128;
    const int b     = blockIdx.z;

    const __half* colsB = g_cols + ((size_t)b * CK_ << 12);

    float acc[4][4][4];
#pragma unroll
    for (int i = 0; i < 4; i++)
#pragma unroll
        for (int j = 0; j < 4; j++)
#pragma unroll
            for (int q = 0; q < 4; q++) acc[i][j][q] = 0.0f;

    auto load_stage = [&](int s, int kt) {
#pragma unroll
        for (int j = 0; j < 2; j++) {           // A: 128 rows x 64B
            int piece = tid + j * 256;
            int row = piece >> 2, seg = piece & 3;
            cpasync16(smem_u32(&As[s][row][seg * 8]),
                      g_w + (size_t)(mBase + row) * CK_ + kt + seg * 8);
        }
#pragma unroll
        for (int j = 0; j < 2; j++) {           // B: 32 rows x 256B
            int piece = tid + j * 256;
            int row = piece >> 4, seg = piece & 15;
            cpasync16(smem_u32(&Bs[s][row][seg * 8]),
                      colsB + (((size_t)(kt + row)) << 12) + nBase + seg * 8);
        }
        asm volatile("cp.async.commit_group;" ::: "memory");
    };

    load_stage(0, 0);

    for (int i = 0; i < NKIT; i++) {
        int s = i & 1;
        if (i + 1 < NKIT) {
            load_stage(s ^ 1, (i + 1) * BKG);
            asm volatile("cp.async.wait_group 1;" ::: "memory");
        } else {
            asm volatile("cp.async.wait_group 0;" ::: "memory");
        }
        __syncthreads();

#pragma unroll
        for (int ks = 0; ks < 2; ks++) {
            int k0 = ks * 16;
            uint32_t a[4][4];
#pragma unroll
            for (int mt = 0; mt < 4; mt++) {
                uint32_t addr = smem_u32(
                    &As[s][wm * 64 + mt * 16 + (lid & 15)][k0 + ((lid >> 4) & 1) * 8]);
                ldsm_x4(a[mt], addr);
            }
            uint32_t bf[2][4];
#pragma unroll
            for (int pr = 0; pr < 2; pr++) {
                uint32_t addr = smem_u32(
                    &Bs[s][k0 + (lid & 15)][wn * 32 + pr * 16 + ((lid >> 4) & 1) * 8]);
                ldsm_x4_t(bf[pr], addr);
            }
#pragma unroll
            for (int mt = 0; mt < 4; mt++)
#pragma unroll
                for (int nt = 0; nt < 4; nt++)
                    mma_f16(acc[mt][nt], a[mt],
                            bf[nt >> 1][(nt & 1) * 2], bf[nt >> 1][(nt & 1) * 2 + 1]);
        }
        __syncthreads();
    }

    // Epilogue
    const int r  = lid >> 2;
    const int cc = (lid & 3) * 2;
#pragma unroll
    for (int mt = 0; mt < 4; mt++) {
        int oc0 = mBase + wm * 64 + mt * 16 + r;
        float bz0 = bias[oc0];
        float bz1 = bias[oc0 + 8];
        float* o0 = out + (((size_t)(b * OC_ + oc0)) << 12) + nBase;
        float* o1 = out + (((size_t)(b * OC_ + oc0 + 8)) << 12) + nBase;
#pragma unroll
        for (int nt = 0; nt < 4; nt++) {
            int px = wn * 32 + nt * 8 + cc;
            float2 v0 = make_float2(acc[mt][nt][0] + bz0, acc[mt][nt][1] + bz0);
            float2 v1 = make_float2(acc[mt][nt][2] + bz1, acc[mt][nt][3] + bz1);
            *(float2*)(o0 + px) = v0;
            *(float2*)(o1 + px) = v1;
        }
    }
}

// ---------------------------------------------------------------------------
extern "C" void kernel_launch(void* const* d_in, const int* in_sizes, int n_in,
                              void* d_out, int out_size) {
    const float* x      = (const float*)d_in[0];
    const float* offset = (const float*)d_in[1];
    const float* mask   = (const float*)d_in[2];
    const float* weight = (const float*)d_in[3];
    const float* bias   = (const float*)d_in[4];
    float* out          = (float*)d_out;

    prep_kernel<<<(B_ * K_ * HW_ + 255) / 256, 256>>>(offset, mask);
    wsplit_kernel<<<(OC_ * CK_ + 255) / 256, 256>>>(weight);
    {
        dim3 grid(128, 8, 8);   // pix tiles, c tiles, batch
        transpose_kernel<<<grid, 256>>>(x);
    }
    {
        dim3 grid(HW_ / 32, B_);
        im2col_kernel<<<grid, 256>>>();
    }
    {
        dim3 grid(HW_ / 128, OC_ / 128, B_);
        gemm_mma_kernel<<<grid, 256>>>(bias, out);
    }
}